// round 6
// baseline (speedup 1.0000x reference)
#include <cuda_runtime.h>

#define BS 64
#define NUM_ACTION 125
#define NUM_NOUN 352
#define NUM_CLS (NUM_ACTION + NUM_NOUN)   // 477
#define DD 5
#define HW 1024                            // 32*32
#define CH_TOTAL ((64 + NUM_ACTION + NUM_NOUN) * DD)  // 2705
#define CONF_BASE (63 * DD)                // channel 63 -> pred channels 315..319
#define NEG_INF (-__int_as_float(0x7f800000))
#define NPL 15                             // logits per lane: 15*32=480 >= 477

__device__ float2 g_losses[BS];
__device__ unsigned int g_done = 0;

__device__ __forceinline__ void amax_upd(float v, int s, float& bv, int& bs_) {
    if (v > bv || (v == bv && s < bs_)) { bv = v; bs_ = s; }
}

__global__ void __launch_bounds__(32) fused_kernel(
    const float* __restrict__ pred,
    const int* __restrict__ action_gt,
    const int* __restrict__ noun_gt,
    float* __restrict__ out)
{
    const int b    = blockIdx.x;
    const int lane = threadIdx.x;
    const float* base = pred + (size_t)b * CH_TOTAL * HW;
    const float4* conf4 = (const float4*)(base + (size_t)CONF_BASE * HW); // 1280 float4

    // ---- Phase 1: warp argmax over s = hw*5 + d (first-max tie-break) ----
    // 4 independent accumulator chains (one per float4 component)
    float bvx = NEG_INF, bvy = NEG_INF, bvz = NEG_INF, bvw = NEG_INF;
    int   bix = 0x7fffffff, biy = 0x7fffffff, biz = 0x7fffffff, biw = 0x7fffffff;
    #pragma unroll
    for (int k = 0; k < 40; k++) {
        const int i4 = lane + 32 * k;       // < 1280, coalesced
        const float4 v = conf4[i4];
        const int j = i4 * 4;
        const int d = j >> 10, hw = j & 1023;  // no d-boundary inside a float4
        const int s = hw * DD + d;
        amax_upd(v.x, s,          bvx, bix);
        amax_upd(v.y, s + DD,     bvy, biy);
        amax_upd(v.z, s + 2 * DD, bvz, biz);
        amax_upd(v.w, s + 3 * DD, bvw, biw);
    }
    amax_upd(bvy, biy, bvx, bix);
    amax_upd(bvw, biw, bvz, biz);
    amax_upd(bvz, biz, bvx, bix);
    // xor-butterfly: every lane ends with the global (val, min-idx)
    #pragma unroll
    for (int off = 16; off > 0; off >>= 1) {
        float ov = __shfl_xor_sync(0xffffffff, bvx, off);
        int   os = __shfl_xor_sync(0xffffffff, bix, off);
        amax_upd(ov, os, bvx, bix);
    }
    const int top = bix;
    const int d   = top % DD;
    const int hw  = top / DD;

    // ---- Phase 2: gather 477 logits into registers (15/lane) ----
    const float* gb = base + (size_t)(64 * DD + d) * HW + hw;
    float xv[NPL];
    #pragma unroll
    for (int j = 0; j < NPL; j++) {
        const int c = lane + 32 * j;
        xv[j] = (c < NUM_CLS) ? gb[(size_t)c * DD * HW] : NEG_INF;
    }
    // lane 0 fetches the 2 CE logits directly (will be L1/L2 hits)
    float ce_a = 0.f, ce_n = 0.f;
    if (lane == 0) {
        ce_a = gb[(size_t)action_gt[b] * DD * HW];
        ce_n = gb[(size_t)(NUM_ACTION + noun_gt[b]) * DD * HW];
    }

    // ---- Phase 3: dual logsumexp from registers ----
    float ma = NEG_INF, mn = NEG_INF;
    #pragma unroll
    for (int j = 0; j < NPL; j++) {
        const int c = lane + 32 * j;
        if (c < NUM_ACTION)      ma = fmaxf(ma, xv[j]);
        else if (c < NUM_CLS)    mn = fmaxf(mn, xv[j]);
    }
    #pragma unroll
    for (int off = 16; off > 0; off >>= 1) {
        ma = fmaxf(ma, __shfl_xor_sync(0xffffffff, ma, off));
        mn = fmaxf(mn, __shfl_xor_sync(0xffffffff, mn, off));
    }
    float ea = 0.f, en = 0.f;
    #pragma unroll
    for (int j = 0; j < NPL; j++) {
        const int c = lane + 32 * j;
        if (c < NUM_ACTION)      ea += __expf(xv[j] - ma);
        else if (c < NUM_CLS)    en += __expf(xv[j] - mn);
    }
    #pragma unroll
    for (int off = 16; off > 0; off >>= 1) {
        ea += __shfl_xor_sync(0xffffffff, ea, off);
        en += __shfl_xor_sync(0xffffffff, en, off);
    }

    if (lane == 0) {
        float2 lp;
        lp.x = (ma + __logf(ea)) - ce_a;
        lp.y = (mn + __logf(en)) - ce_n;
        g_losses[b] = lp;
        __threadfence();           // release before done-count
    }

    // ---- tail: last warp reduces 64 partials deterministically ----
    unsigned int cnt = 0;
    if (lane == 0) cnt = atomicAdd(&g_done, 1u);
    cnt = __shfl_sync(0xffffffff, cnt, 0);
    if (cnt != BS - 1) return;

    __threadfence();               // acquire: see all CTAs' g_losses
    volatile float2* gl = (volatile float2*)g_losses;
    float sa = gl[lane].x + gl[lane + 32].x;
    float sn = gl[lane].y + gl[lane + 32].y;
    #pragma unroll
    for (int off = 16; off > 0; off >>= 1) {
        sa += __shfl_down_sync(0xffffffff, sa, off);
        sn += __shfl_down_sync(0xffffffff, sn, off);
    }
    if (lane == 0) {
        const float la = sa * 0.5f;
        const float ln = sn * 0.5f;
        out[0] = la + ln;
        out[1] = la;
        out[2] = ln;
        g_done = 0;                // reset for next graph replay
    }
}

extern "C" void kernel_launch(void* const* d_in, const int* in_sizes, int n_in,
                              void* d_out, int out_size)
{
    const float* pred = (const float*)d_in[0];
    const int*   ag   = (const int*)d_in[1];
    const int*   ng   = (const int*)d_in[2];
    float* out = (float*)d_out;

    fused_kernel<<<BS, 32>>>(pred, ag, ng, out);
}